// round 12
// baseline (speedup 1.0000x reference)
#include <cuda_runtime.h>
#include <cuda_bf16.h>
#include <cstdint>
#include <cstddef>

// Pairwise Euclidean distance, B=8192, K=256, D=3072, fp32.
// out[b,k] = sqrt(max(||x||^2 + ||c||^2 - 2 x.c, eps))
// R12: single 256-thread pipeline (256-reg budget), frag-level software
// pipelining: frags for tile i+1 LDSM'd during tile i's MMAs (stage ring
// write-ahead 2 makes stage i+1 visible at iter i). B via cp.async (bf16
// prepass), A via LDG+cvt+STS with fused ||x||^2.

#define BB 8192
#define KK 256
#define DD 3072
#define BM 128
#define BN 128
#define BK 32
#define NT (DD / BK)            // 96 k-tiles
#define NTHREADS 256
#define EPS_F 1e-12f

#define ROW_B 80                // 32 bf16 + pad: ldmatrix conflict-free
#define TILE_B (128 * ROW_B)    // 10240
#define STAGE_B (2 * TILE_B)    // 20480 (A then B)
#define NSTAGE 4
#define OFF_XSQ  (NSTAGE * STAGE_B)          // 81920
#define OFF_CSQ  (OFF_XSQ + 512)
#define SMEM_BYTES (OFF_CSQ + 512)           // 82944

__device__ __nv_bfloat16 g_cb[KK * DD];
__device__ float g_csq[KK];

static __device__ __forceinline__ uint32_t s2u(const void* p) {
    uint32_t a;
    asm("{.reg .u64 t; cvta.to.shared.u64 t, %1; cvt.u32.u64 %0, t;}"
        : "=r"(a) : "l"(p));
    return a;
}

#define LDSM_X4(r0, r1, r2, r3, a)                                            \
    asm volatile("ldmatrix.sync.aligned.m8n8.x4.shared.b16 {%0,%1,%2,%3}, [%4];" \
                 : "=r"(r0), "=r"(r1), "=r"(r2), "=r"(r3) : "r"(a))

#define MMA(acc, a, b0, b1)                                                   \
    asm volatile("mma.sync.aligned.m16n8k16.row.col.f32.bf16.bf16.f32 "       \
                 "{%0,%1,%2,%3}, {%4,%5,%6,%7}, {%8,%9}, {%0,%1,%2,%3};\n"    \
                 : "+f"((acc)[0]), "+f"((acc)[1]), "+f"((acc)[2]), "+f"((acc)[3]) \
                 : "r"((a)[0]), "r"((a)[1]), "r"((a)[2]), "r"((a)[3]),        \
                   "r"(b0), "r"(b1))

// load all 6 fragment sets (2 A + 4 B) for one ks half of a tile
#define LDSM6(av, bv, stA, stB, kof)                                          \
    do {                                                                      \
        LDSM_X4((av)[0][0], (av)[0][1], (av)[0][2], (av)[0][3], (stA) + (kof)); \
        LDSM_X4((av)[1][0], (av)[1][1], (av)[1][2], (av)[1][3],               \
                (stA) + (kof) + 16 * ROW_B);                                  \
        LDSM_X4((bv)[0][0], (bv)[0][1], (bv)[0][2], (bv)[0][3], (stB) + (kof)); \
        LDSM_X4((bv)[1][0], (bv)[1][1], (bv)[1][2], (bv)[1][3],               \
                (stB) + (kof) + 16 * ROW_B);                                  \
        LDSM_X4((bv)[2][0], (bv)[2][1], (bv)[2][2], (bv)[2][3],               \
                (stB) + (kof) + 32 * ROW_B);                                  \
        LDSM_X4((bv)[3][0], (bv)[3][1], (bv)[3][2], (bv)[3][3],               \
                (stB) + (kof) + 48 * ROW_B);                                  \
    } while (0)

#define MMA16(av, bv)                                                         \
    do {                                                                      \
        _Pragma("unroll")                                                     \
        for (int im = 0; im < 2; im++) {                                      \
            MMA(acc[im][0], (av)[im], (bv)[0][0], (bv)[0][2]);                \
            MMA(acc[im][1], (av)[im], (bv)[0][1], (bv)[0][3]);                \
            MMA(acc[im][2], (av)[im], (bv)[1][0], (bv)[1][2]);                \
            MMA(acc[im][3], (av)[im], (bv)[1][1], (bv)[1][3]);                \
            MMA(acc[im][4], (av)[im], (bv)[2][0], (bv)[2][2]);                \
            MMA(acc[im][5], (av)[im], (bv)[2][1], (bv)[2][3]);                \
            MMA(acc[im][6], (av)[im], (bv)[3][0], (bv)[3][2]);                \
            MMA(acc[im][7], (av)[im], (bv)[3][1], (bv)[3][3]);                \
        }                                                                     \
    } while (0)

// ---------------- prepass: centers fp32 -> bf16, csq ----------------
__global__ void __launch_bounds__(128, 8)
prep_c_kernel(const float* __restrict__ C)
{
    const int row = blockIdx.x;
    const float4* src = reinterpret_cast<const float4*>(C + (size_t)row * DD);
    uint2* dst = reinterpret_cast<uint2*>(g_cb + (size_t)row * DD);
    float s = 0.f;
    #pragma unroll
    for (int i = 0; i < 6; i++) {
        const int q = threadIdx.x + i * 128;
        float4 v = src[q];
        s += v.x * v.x + v.y * v.y + v.z * v.z + v.w * v.w;
        __nv_bfloat162 p0 = __float22bfloat162_rn(make_float2(v.x, v.y));
        __nv_bfloat162 p1 = __float22bfloat162_rn(make_float2(v.z, v.w));
        uint2 u;
        u.x = *reinterpret_cast<uint32_t*>(&p0);
        u.y = *reinterpret_cast<uint32_t*>(&p1);
        dst[q] = u;
    }
    #pragma unroll
    for (int o = 16; o > 0; o >>= 1)
        s += __shfl_xor_sync(0xFFFFFFFFu, s, o);
    __shared__ float red[4];
    if ((threadIdx.x & 31) == 0) red[threadIdx.x >> 5] = s;
    __syncthreads();
    if (threadIdx.x == 0)
        g_csq[row] = red[0] + red[1] + red[2] + red[3];
}

// ---------------- main GEMM ----------------
__global__ void __launch_bounds__(NTHREADS, 1)
rbf_pipe_kernel(const float* __restrict__ X, float* __restrict__ out)
{
    extern __shared__ __align__(16) char smem[];
    const uint32_t sb = s2u(smem);
    const int tid  = threadIdx.x;
    const int wid  = tid >> 5;
    const int lane = tid & 31;
    const int bm = blockIdx.y;
    const int bn = blockIdx.x;

    float* xsq_s = (float*)(smem + OFF_XSQ);
    float* csq_s = (float*)(smem + OFF_CSQ);
    if (tid < 128) {
        xsq_s[tid] = 0.f;
        csq_s[tid] = g_csq[bn * BN + tid];
    }

    // ---- A producer: quarter-warp = 1 cache line (R8-proven mapping) ----
    const int lr = tid >> 3;           // rows lr + 32p
    const int c4 = tid & 7;
    const float4* pA0 = reinterpret_cast<const float4*>(
        X + (size_t)(bm * BM + lr) * DD) + c4;
    const float4* pA1 = pA0 + 32 * (DD / 4);
    const float4* pA2 = pA0 + 64 * (DD / 4);
    const float4* pA3 = pA0 + 96 * (DD / 4);
    const uint32_t adst = (uint32_t)lr * ROW_B + (uint32_t)c4 * 8;
    float4 ra[4];
    float xs[4] = {0.f, 0.f, 0.f, 0.f};

    auto ldgA = [&]() {                // one k-tile: 8 float4 advance
        ra[0] = *pA0; ra[1] = *pA1; ra[2] = *pA2; ra[3] = *pA3;
        pA0 += 8; pA1 += 8; pA2 += 8; pA3 += 8;
    };
    auto stsA = [&](int i) {
        const uint32_t base = sb + (uint32_t)(i & 3) * STAGE_B + adst;
        #pragma unroll
        for (int p = 0; p < 4; p++) {
            float4 v = ra[p];
            xs[p] += v.x * v.x + v.y * v.y + v.z * v.z + v.w * v.w;
            __nv_bfloat162 q0 = __float22bfloat162_rn(make_float2(v.x, v.y));
            __nv_bfloat162 q1 = __float22bfloat162_rn(make_float2(v.z, v.w));
            asm volatile("st.shared.v2.b32 [%0], {%1,%2};"
                         :: "r"(base + (uint32_t)(p * 32 * ROW_B)),
                            "r"(*reinterpret_cast<uint32_t*>(&q0)),
                            "r"(*reinterpret_cast<uint32_t*>(&q1)) : "memory");
        }
    };

    // ---- B producer: cp.async bf16, rows br/br+64, running pointers ----
    const int br = tid >> 2;
    const int bc = tid & 3;
    const __nv_bfloat16* pB0 = g_cb + (size_t)(bn * BN + br) * DD + bc * 8;
    const __nv_bfloat16* pB1 = pB0 + (size_t)64 * DD;
    const uint32_t bdst = (uint32_t)br * ROW_B + (uint32_t)bc * 16 + (uint32_t)TILE_B;
    auto cpB = [&](int i) {
        const uint32_t base = sb + (uint32_t)(i & 3) * STAGE_B + bdst;
        asm volatile("cp.async.cg.shared.global [%0], [%1], 16;"
                     :: "r"(base), "l"(pB0) : "memory");
        asm volatile("cp.async.cg.shared.global [%0], [%1], 16;"
                     :: "r"(base + (uint32_t)(64 * ROW_B)), "l"(pB1) : "memory");
        asm volatile("cp.async.commit_group;" ::: "memory");
        pB0 += 32; pB1 += 32;          // one k-tile
    };

    // ---- compute mapping: 4(M)x2(N) warps, warp tile 32x64 ----
    const int wm = wid & 3;
    const int wn = wid >> 2;
    const int fr = lane >> 2;
    const int fc = (lane & 3) * 2;
    const int lg = lane >> 3;
    const int ri = lane & 7;
    const uint32_t lm_off = (uint32_t)(((lg & 1) * 8 + ri) * ROW_B + (lg >> 1) * 16);
    const uint32_t a_off = (uint32_t)(wm * 32 * ROW_B) + lm_off;
    const uint32_t b_off = (uint32_t)(wn * 64 * ROW_B) + lm_off + (uint32_t)TILE_B;

    float acc[2][8][4];
    #pragma unroll
    for (int i = 0; i < 2; i++)
        #pragma unroll
        for (int j = 0; j < 8; j++)
            #pragma unroll
            for (int q = 0; q < 4; q++) acc[i][j][q] = 0.f;

    // frag double buffer: X = ks0 of current tile, Y = ks1
    uint32_t ax[2][4], bx[4][4], ay[2][4], by[4][4];

    // ---- prologue: fill stages 0-2 (A) and 0-2 (B); ra ends holding tile 2 ----
    cpB(0); cpB(1); cpB(2);
    ldgA(); stsA(0);
    ldgA(); stsA(1);
    ldgA();                            // ra = tile 2 (consumed by iter 0's stsA(2))
    asm volatile("cp.async.wait_group 1;" ::: "memory");   // B0, B1 complete
    __syncthreads();
    {   // preload ks0 frags of tile 0
        const uint32_t stA = sb + a_off;
        const uint32_t stB = sb + b_off;
        LDSM6(ax, bx, stA, stB, 0u);
    }

    // ---- mainloop ----
    #pragma unroll 1
    for (int i = 0; i < NT; i++) {
        const uint32_t st  = sb + (uint32_t)(i & 3) * STAGE_B;
        const uint32_t stA = st + a_off;
        const uint32_t stB = st + b_off;

        // phase 1: fetch ks1 frags, crunch ks0
        LDSM6(ay, by, stA, stB, 32u);
        MMA16(ax, bx);

        // producers (overlap tensor drain)
        if (i + 2 < NT) stsA(i + 2);
        if (i + 3 < NT) ldgA();

        // phase 2: fetch NEXT TILE's ks0 frags (stage i+1 already visible),
        // crunch ks1
        if (i + 1 < NT) {
            const uint32_t sn  = sb + (uint32_t)((i + 1) & 3) * STAGE_B;
            LDSM6(ax, bx, sn + a_off, sn + b_off, 0u);
        }
        MMA16(ay, by);

        if (i + 3 < NT) cpB(i + 3);
        asm volatile("cp.async.wait_group 1;" ::: "memory");
        __syncthreads();
    }

    // ---- norms ----
    #pragma unroll
    for (int p = 0; p < 4; p++)
        atomicAdd(&xsq_s[p * 32 + lr], xs[p]);
    __syncthreads();

    // ---- fused epilogue ----
    #pragma unroll
    for (int im = 0; im < 2; im++) {
        #pragma unroll
        for (int hf = 0; hf < 2; hf++) {
            const int row = wm * 32 + im * 16 + hf * 8 + fr;
            const float xq = xsq_s[row];
            float* orow = out + ((size_t)bm * BM + row) * KK + bn * BN;
            #pragma unroll
            for (int j = 0; j < 8; j++) {
                const int col = wn * 64 + j * 8 + fc;
                const float d0 = sqrtf(fmaxf(
                    xq + csq_s[col] - 2.f * acc[im][j][hf * 2 + 0], EPS_F));
                const float d1 = sqrtf(fmaxf(
                    xq + csq_s[col + 1] - 2.f * acc[im][j][hf * 2 + 1], EPS_F));
                *reinterpret_cast<float2*>(orow + col) = make_float2(d0, d1);
            }
        }
    }
}

extern "C" void kernel_launch(void* const* d_in, const int* in_sizes, int n_in,
                              void* d_out, int out_size)
{
    const float* X = (const float*)d_in[0];
    const float* C = (const float*)d_in[1];
    float* out = (float*)d_out;

    prep_c_kernel<<<KK, 128>>>(C);

    cudaFuncSetAttribute(rbf_pipe_kernel,
                         cudaFuncAttributeMaxDynamicSharedMemorySize, SMEM_BYTES);
    dim3 grid(KK / BN, BB / BM);
    rbf_pipe_kernel<<<grid, NTHREADS, SMEM_BYTES>>>(X, out);
}

// round 13
// speedup vs baseline: 1.2625x; 1.2625x over previous
#include <cuda_runtime.h>
#include <cuda_bf16.h>
#include <cstdint>
#include <cstddef>

// Pairwise Euclidean distance, B=8192, K=256, D=3072, fp32.
// out[b,k] = sqrt(max(||x||^2 + ||c||^2 - 2 x.c, eps))
// R13 = R8 (proven 64.0us) with ONE change: running-pointer global addressing
// (kills per-tile IMAD.WIDE chains, alu pipe 26% -> ~14%). Same op order,
// same memory patterns, same barriers, same epilogue.

#define BB 8192
#define KK 256
#define DD 3072
#define BM 128
#define BN 128
#define BK 32
#define NT (DD / BK)            // 96 k-tiles
#define NTG (NT / 2)            // 48 per group
#define NTHREADS 512
#define EPS_F 1e-12f

#define ROW_B 80                // 32 bf16 + pad: ldmatrix conflict-free
#define TILE_B (128 * ROW_B)    // 10240
#define STAGE_B (2 * TILE_B)    // 20480 (A then B)
#define GSTEP (2 * STAGE_B)     // group-local stage stride
#define NSTAGE 8
#define OFF_XSQ  (NSTAGE * STAGE_B)          // 163840
#define OFF_CSQ  (OFF_XSQ + 512)
#define SMEM_BYTES (OFF_CSQ + 512)
#define STASH_STRIDE 132

__device__ __nv_bfloat16 g_cb[KK * DD];
__device__ float g_csq[KK];

static __device__ __forceinline__ uint32_t s2u(const void* p) {
    uint32_t a;
    asm("{.reg .u64 t; cvta.to.shared.u64 t, %1; cvt.u32.u64 %0, t;}"
        : "=r"(a) : "l"(p));
    return a;
}

#define LDSM_X4(r0, r1, r2, r3, a)                                            \
    asm volatile("ldmatrix.sync.aligned.m8n8.x4.shared.b16 {%0,%1,%2,%3}, [%4];" \
                 : "=r"(r0), "=r"(r1), "=r"(r2), "=r"(r3) : "r"(a))

#define GBAR(id) asm volatile("bar.sync %0, 256;" :: "r"(id) : "memory")

// ---------------- prepass: centers fp32 -> bf16, csq ----------------
__global__ void __launch_bounds__(128, 8)
prep_c_kernel(const float* __restrict__ C)
{
    const int row = blockIdx.x;
    const float4* src = reinterpret_cast<const float4*>(C + (size_t)row * DD);
    uint2* dst = reinterpret_cast<uint2*>(g_cb + (size_t)row * DD);
    float s = 0.f;
    #pragma unroll
    for (int i = 0; i < 6; i++) {
        const int q = threadIdx.x + i * 128;
        float4 v = src[q];
        s += v.x * v.x + v.y * v.y + v.z * v.z + v.w * v.w;
        __nv_bfloat162 p0 = __float22bfloat162_rn(make_float2(v.x, v.y));
        __nv_bfloat162 p1 = __float22bfloat162_rn(make_float2(v.z, v.w));
        uint2 u;
        u.x = *reinterpret_cast<uint32_t*>(&p0);
        u.y = *reinterpret_cast<uint32_t*>(&p1);
        dst[q] = u;
    }
    #pragma unroll
    for (int o = 16; o > 0; o >>= 1)
        s += __shfl_xor_sync(0xFFFFFFFFu, s, o);
    __shared__ float red[4];
    if ((threadIdx.x & 31) == 0) red[threadIdx.x >> 5] = s;
    __syncthreads();
    if (threadIdx.x == 0)
        g_csq[row] = red[0] + red[1] + red[2] + red[3];
}

// ---------------- main GEMM ----------------
__global__ void __launch_bounds__(NTHREADS, 1)
rbf_dual_kernel(const float* __restrict__ X, float* __restrict__ out)
{
    extern __shared__ __align__(16) char smem[];
    const uint32_t sb = s2u(smem);
    const int tid  = threadIdx.x;
    const int wid  = tid >> 5;
    const int lane = tid & 31;
    const int bm = blockIdx.y;
    const int bn = blockIdx.x;

    const int g   = wid >> 3;          // k-parity group 0/1
    const int gt  = tid & 255;
    const int bar = g + 1;

    float* xsq_s = (float*)(smem + OFF_XSQ);
    float* csq_s = (float*)(smem + OFF_CSQ);
    if (tid < 128) {
        xsq_s[tid] = 0.f;
        csq_s[tid] = g_csq[bn * BN + tid];
    }
    __syncthreads();

    const uint32_t sbg = sb + (uint32_t)g * STAGE_B;

    // ---- A producer (R8 mapping): rows ar+32j, quarter-warp = 1 cache line ----
    // Running pointers: advance by 16 float4 (= 2 global k-tiles) per call.
    const int ar = gt >> 3;            // 0..31
    const int c4 = gt & 7;
    const float4* pA0 = reinterpret_cast<const float4*>(
        X + (size_t)(bm * BM + ar) * DD + g * BK) + c4;
    const float4* pA1 = pA0 + 32 * (DD / 4);
    const float4* pA2 = pA0 + 64 * (DD / 4);
    const float4* pA3 = pA0 + 96 * (DD / 4);
    const uint32_t adst = (uint32_t)ar * ROW_B + (uint32_t)c4 * 8;
    float4 ra[4];
    float xs[4] = {0.f, 0.f, 0.f, 0.f};

    auto ldgA = [&]() {
        ra[0] = *pA0; ra[1] = *pA1; ra[2] = *pA2; ra[3] = *pA3;
        pA0 += 16; pA1 += 16; pA2 += 16; pA3 += 16;
    };
    auto stsA = [&](int i) {
        const uint32_t base = sbg + (uint32_t)(i & 3) * GSTEP + adst;
        #pragma unroll
        for (int j = 0; j < 4; j++) {
            float4 v = ra[j];
            xs[j] += v.x * v.x + v.y * v.y + v.z * v.z + v.w * v.w;
            __nv_bfloat162 q0 = __float22bfloat162_rn(make_float2(v.x, v.y));
            __nv_bfloat162 q1 = __float22bfloat162_rn(make_float2(v.z, v.w));
            asm volatile("st.shared.v2.b32 [%0], {%1,%2};"
                         :: "r"(base + (uint32_t)(j * 32 * ROW_B)),
                            "r"(*reinterpret_cast<uint32_t*>(&q0)),
                            "r"(*reinterpret_cast<uint32_t*>(&q1)) : "memory");
        }
    };

    // ---- B producer (R8 mapping): cp.async, running pointers ----
    const int br = gt >> 2;            // rows br, br+64
    const int bc = gt & 3;
    const __nv_bfloat16* pB0 = g_cb + (size_t)(bn * BN + br) * DD + g * BK + bc * 8;
    const __nv_bfloat16* pB1 = pB0 + (size_t)64 * DD;
    const uint32_t bdst = (uint32_t)br * ROW_B + (uint32_t)bc * 16 + (uint32_t)TILE_B;
    auto cpB = [&](int i) {
        const uint32_t base = sbg + (uint32_t)(i & 3) * GSTEP + bdst;
        asm volatile("cp.async.cg.shared.global [%0], [%1], 16;"
                     :: "r"(base), "l"(pB0) : "memory");
        asm volatile("cp.async.cg.shared.global [%0], [%1], 16;"
                     :: "r"(base + (uint32_t)(64 * ROW_B)), "l"(pB1) : "memory");
        asm volatile("cp.async.commit_group;" ::: "memory");
        pB0 += 64; pB1 += 64;          // 2 global k-tiles of bf16
    };

    // ---- compute mapping: per group 4(M)x2(N), warp tile 32x64 ----
    const int w8 = wid & 7;
    const int wm = w8 & 3;
    const int wn = w8 >> 2;
    const int fr = lane >> 2;
    const int fc = (lane & 3) * 2;
    const int lg = lane >> 3;
    const int ri = lane & 7;
    const uint32_t lm_off = (uint32_t)(((lg & 1) * 8 + ri) * ROW_B + (lg >> 1) * 16);
    const uint32_t a_off = (uint32_t)(wm * 32 * ROW_B) + lm_off;
    const uint32_t b_off = (uint32_t)(wn * 64 * ROW_B) + lm_off + (uint32_t)TILE_B;

    float acc[2][8][4];
    #pragma unroll
    for (int i = 0; i < 2; i++)
        #pragma unroll
        for (int j = 0; j < 8; j++)
            #pragma unroll
            for (int q = 0; q < 4; q++) acc[i][j][q] = 0.f;

    // ---- prologue (identical order to R8) ----
    ldgA();
    cpB(0);
    stsA(0);
    ldgA();
    cpB(1);
    asm volatile("cp.async.wait_group 1;" ::: "memory");
    GBAR(bar);

    // ---- mainloop (identical order to R8) ----
    #pragma unroll 1
    for (int i = 0; i < NTG; i++) {
        const uint32_t st = sbg + (uint32_t)(i & 3) * GSTEP;
        const uint32_t stA = st + a_off;
        const uint32_t stB = st + b_off;

        #pragma unroll
        for (int ks = 0; ks < 2; ks++) {
            const uint32_t kof = (uint32_t)ks * 32;
            uint32_t a[2][4], b[4][4];
            LDSM_X4(a[0][0], a[0][1], a[0][2], a[0][3], stA + kof);
            LDSM_X4(a[1][0], a[1][1], a[1][2], a[1][3], stA + kof + 16 * ROW_B);
            LDSM_X4(b[0][0], b[0][1], b[0][2], b[0][3], stB + kof);
            LDSM_X4(b[1][0], b[1][1], b[1][2], b[1][3], stB + kof + 16 * ROW_B);
            LDSM_X4(b[2][0], b[2][1], b[2][2], b[2][3], stB + kof + 32 * ROW_B);
            LDSM_X4(b[3][0], b[3][1], b[3][2], b[3][3], stB + kof + 48 * ROW_B);
            #pragma unroll
            for (int im = 0; im < 2; im++)
                #pragma unroll
                for (int j = 0; j < 8; j++) {
                    const int jb = j >> 1, pp = j & 1;
                    asm volatile(
                        "mma.sync.aligned.m16n8k16.row.col.f32.bf16.bf16.f32 "
                        "{%0,%1,%2,%3}, {%4,%5,%6,%7}, {%8,%9}, {%0,%1,%2,%3};\n"
                        : "+f"(acc[im][j][0]), "+f"(acc[im][j][1]),
                          "+f"(acc[im][j][2]), "+f"(acc[im][j][3])
                        : "r"(a[im][0]), "r"(a[im][1]), "r"(a[im][2]), "r"(a[im][3]),
                          "r"(b[jb][pp]), "r"(b[jb][pp + 2]));
                }
        }

        if (i + 1 < NTG) {
            stsA(i + 1);
            if (i + 2 < NTG) {
                ldgA();
                cpB(i + 2);
                asm volatile("cp.async.wait_group 1;" ::: "memory");
            } else {
                asm volatile("cp.async.wait_group 0;" ::: "memory");
            }
        }
        GBAR(bar);
    }

    // ---- norms ----
    #pragma unroll
    for (int j = 0; j < 4; j++)
        atomicAdd(&xsq_s[j * 32 + ar], xs[j]);
    __syncthreads();

    // ---- split-k merge + fused epilogue (identical to R8) ----
    float* stash = (float*)smem;
    if (g == 1) {
        #pragma unroll
        for (int im = 0; im < 2; im++)
            #pragma unroll
            for (int hf = 0; hf < 2; hf++) {
                const int row = wm * 32 + im * 16 + hf * 8 + fr;
                #pragma unroll
                for (int j = 0; j < 8; j++) {
                    const int col = wn * 64 + j * 8 + fc;
                    *reinterpret_cast<float2*>(&stash[row * STASH_STRIDE + col]) =
                        make_float2(acc[im][j][hf * 2], acc[im][j][hf * 2 + 1]);
                }
            }
    }
    __syncthreads();
    if (g == 0) {
        #pragma unroll
        for (int im = 0; im < 2; im++)
            #pragma unroll
            for (int hf = 0; hf < 2; hf++) {
                const int row = wm * 32 + im * 16 + hf * 8 + fr;
                const float xq = xsq_s[row];
                float* orow = out + ((size_t)bm * BM + row) * KK + bn * BN;
                #pragma unroll
                for (int j = 0; j < 8; j++) {
                    const int col = wn * 64 + j * 8 + fc;
                    const float2 o = *reinterpret_cast<const float2*>(
                        &stash[row * STASH_STRIDE + col]);
                    const float cr0 = acc[im][j][hf * 2] + o.x;
                    const float cr1 = acc[im][j][hf * 2 + 1] + o.y;
                    const float d0 = sqrtf(fmaxf(xq + csq_s[col] - 2.f * cr0, EPS_F));
                    const float d1 = sqrtf(fmaxf(xq + csq_s[col + 1] - 2.f * cr1, EPS_F));
                    *reinterpret_cast<float2*>(orow + col) = make_float2(d0, d1);
                }
            }
    }
}

extern "C" void kernel_launch(void* const* d_in, const int* in_sizes, int n_in,
                              void* d_out, int out_size)
{
    const float* X = (const float*)d_in[0];
    const float* C = (const float*)d_in[1];
    float* out = (float*)d_out;

    prep_c_kernel<<<KK, 128>>>(C);

    cudaFuncSetAttribute(rbf_dual_kernel,
                         cudaFuncAttributeMaxDynamicSharedMemorySize, SMEM_BYTES);
    dim3 grid(KK / BN, BB / BM);
    rbf_dual_kernel<<<grid, NTHREADS, SMEM_BYTES>>>(X, out);
}